// round 8
// baseline (speedup 1.0000x reference)
#include <cuda_runtime.h>
#include <math.h>

#define IMG_W 128
#define IMG_H 128
#define MAX_N 4096
#define TILE_W 8
#define TILE_H 4
#define SEGS   16
#define SLOTS  12
#define NTILES ((IMG_W / TILE_W) * (IMG_H / TILE_H))   // 512
#define NPERS  296                                      // ~2 blocks/SM * 148

// Per-gaussian params, 4 x float4:
//  [0] minu, maxu, minv, maxv    (reference box - used in pixel mask)
//  [1] u, v, ia, ibc
//  [2] idd, op, z, pad
//  [3] col0, col1, col2, pad
__device__ float4 g_prm[MAX_N * 4];
// Tightened cull box (refbox ∩ 3-sigma ellipse extents) - cull only.
__device__ float4 g_cbox[MAX_N];
// Work-stealing ticket counter (reset by gs_precompute each launch).
__device__ unsigned int g_ticket;

// Center-out orderings for tile coordinates (hot tiles first).
__constant__ int ord16[16] = {8,7,9,6,10,5,11,4,12,3,13,2,14,1,15,0};
__constant__ int ord32[32] = {16,15,17,14,18,13,19,12,20,11,21,10,22,9,23,8,
                              24,7,25,6,26,5,27,4,28,3,29,2,30,1,31,0};

__global__ void gs_precompute(const float* __restrict__ means,
                              const float* __restrict__ scales,
                              const float* __restrict__ rots,
                              const float* __restrict__ opac,
                              const float* __restrict__ feats,
                              const float* __restrict__ cam,
                              const float* __restrict__ focal_p,
                              const float* __restrict__ cx_p,
                              const float* __restrict__ cy_p,
                              int N)
{
    int g = blockIdx.x * blockDim.x + threadIdx.x;
    if (g == 0) g_ticket = 0;           // reset work-stealing counter
    if (g >= N) return;

    const float f  = focal_p[0];
    const float cx = cx_p[0];
    const float cy = cy_p[0];

    float R[3][3], t[3];
    #pragma unroll
    for (int i = 0; i < 3; i++) {
        #pragma unroll
        for (int k = 0; k < 3; k++) R[i][k] = cam[i * 4 + k];
        t[i] = cam[i * 4 + 3];
    }

    float mean[3], sc[3];
    #pragma unroll
    for (int k = 0; k < 3; k++) {
        mean[k] = means[g * 3 + k];
        sc[k]   = expf(scales[g * 3 + k]);
    }

    float qw = rots[g * 4 + 0], qx = rots[g * 4 + 1];
    float qy = rots[g * 4 + 2], qz = rots[g * 4 + 3];
    float two_s = 2.0f / (qw * qw + qx * qx + qy * qy + qz * qz);
    float xx = qx * qx * two_s, xy = qx * qy * two_s, xz = qx * qz * two_s;
    float yw = qy * qw * two_s, yy = qy * qy * two_s, yz = qy * qz * two_s;
    float zw = qz * qw * two_s, zz = qz * qz * two_s, xw = qx * qw * two_s;
    float M[3][3];
    M[0][0] = 1.0f - (yy + zz); M[0][1] = xy - zw;          M[0][2] = xz + yw;
    M[1][0] = xy + zw;          M[1][1] = 1.0f - (xx + zz); M[1][2] = yz - xw;
    M[2][0] = xz - yw;          M[2][1] = yz + xw;          M[2][2] = 1.0f - (xx + yy);

    float mc[3];
    #pragma unroll
    for (int i = 0; i < 3; i++)
        mc[i] = R[i][0] * mean[0] + R[i][1] * mean[1] + R[i][2] * mean[2] + t[i];
    float z = mc[2];
    float u = mc[0] / z * f + cx;
    float v = mc[1] / z * f + cy;

    float J0[3], J1[3];
    #pragma unroll
    for (int k = 0; k < 3; k++) {
        J0[k] = f * R[0][k] - cx * R[2][k];
        J1[k] = f * R[1][k] - cy * R[2][k];
    }

    float V0[3], V1[3];
    #pragma unroll
    for (int k = 0; k < 3; k++) {
        V0[k] = (J0[0] * M[0][k] + J0[1] * M[1][k] + J0[2] * M[2][k]) * sc[k];
        V1[k] = (J1[0] * M[0][k] + J1[1] * M[1][k] + J1[2] * M[2][k]) * sc[k];
    }

    float inv_z2 = 1.0f / (z * z);
    float a = (V0[0] * V0[0] + V0[1] * V0[1] + V0[2] * V0[2]) * inv_z2;
    float b = (V0[0] * V1[0] + V0[1] * V1[1] + V0[2] * V1[2]) * inv_z2;
    float d = (V1[0] * V1[0] + V1[1] * V1[1] + V1[2] * V1[2]) * inv_z2;
    float det = a * d - b * b;
    float ia  = d / det;
    float ibc = -(b + b) / det;
    float idd = a / det;

    float op = 1.0f / (1.0f + expf(-opac[g]));
    float c0 = 1.0f / (1.0f + expf(-feats[g * 3 + 0]));
    float c1 = 1.0f / (1.0f + expf(-feats[g * 3 + 1]));
    float c2 = 1.0f / (1.0f + expf(-feats[g * 3 + 2]));

    float smax = fmaxf(sc[0], fmaxf(sc[1], sc[2]));
    float radius = smax * f / z * 3.0f;

    float minu = fmaxf(0.0f, truncf(u - radius));
    float maxu = truncf(u + radius);
    float minv = fmaxf(0.0f, truncf(v - radius));
    float maxv = truncf(v + radius);

    g_prm[g * 4 + 0] = make_float4(minu, maxu, minv, maxv);
    g_prm[g * 4 + 1] = make_float4(u, v, ia, ibc);
    g_prm[g * 4 + 2] = make_float4(idd, op, z, 0.0f);
    g_prm[g * 4 + 3] = make_float4(c0, c1, c2, 0.0f);

    // tightened cull box: mask requires in_refbox AND d2<9;
    // d2<9 implies |dx| <= 3*sqrt(cov_xx), |dy| <= 3*sqrt(cov_yy)
    float ru = 3.0f * sqrtf(fmaxf(a, 0.0f));
    float rv = 3.0f * sqrtf(fmaxf(d, 0.0f));
    g_cbox[g] = make_float4(fmaxf(minu, u - ru), fminf(maxu, u + ru),
                            fmaxf(minv, v - rv), fminf(maxv, v + rv));
}

// Persistent blocks pull 8x4 tiles from a global ticket (center-out order).
// Per tile: 16 warps cull+scan 64-gaussian segments, record local strict
// running minima; warp 0 merges segments in order (global running-min ==
// reference depth_buf) with branchless composite.
__global__ __launch_bounds__(SEGS * 32)
void gs_render(float* __restrict__ out, int N)
{
    extern __shared__ char smem_raw[];
    float2*         s_rec = (float2*)smem_raw;                  // [SEGS*SLOTS*32]
    int*            s_cnt = (int*)(s_rec + SEGS * SLOTS * 32);  // [SEGS*32]
    unsigned short* s_gid = (unsigned short*)(s_cnt + SEGS * 32);
    unsigned short* s_idx = s_gid + SEGS * SLOTS * 32;          // [SEGS*segLen]
    __shared__ int s_tile;

    const int warp = threadIdx.x >> 5;
    const int lane = threadIdx.x & 31;

    const int segLen = (N + SEGS - 1) / SEGS;
    const int segBeg = warp * segLen;
    const int segEnd = min(segBeg + segLen, N);
    const float INF = __int_as_float(0x7f800000);

    unsigned short* myidx = s_idx + warp * segLen;
    const int entBase = warp * SLOTS * 32 + lane;

    while (true) {
        if (threadIdx.x == 0) s_tile = (int)atomicAdd(&g_ticket, 1u);
        __syncthreads();
        int tile = s_tile;
        if (tile >= NTILES) break;

        const int tx0 = ord16[tile & 15] * TILE_W;
        const int ty0 = ord32[tile >> 4] * TILE_H;
        const int px_i = tx0 + (lane & (TILE_W - 1));
        const int py_i = ty0 + (lane >> 3);
        const float px = (float)px_i;
        const float py = (float)py_i;
        const float ftx0 = (float)tx0, ftx1 = (float)(tx0 + TILE_W - 1);
        const float fty0 = (float)ty0, fty1 = (float)(ty0 + TILE_H - 1);

        // ---- cull segment against tightened box (order-preserving) ----
        int cnt = 0;
        for (int j = segBeg; j < segEnd; j += 32) {
            int g = j + lane;
            bool ok = false;
            if (g < segEnd) {
                float4 cb = __ldg(&g_cbox[g]);
                ok = (cb.x <= ftx1) & (cb.y >= ftx0) &
                     (cb.z <= fty1) & (cb.w >= fty0);
            }
            unsigned m = __ballot_sync(0xffffffffu, ok);
            if (ok) myidx[cnt + __popc(m & ((1u << lane) - 1u))] = (unsigned short)g;
            cnt += __popc(m);
        }

        // ---- phase A: local strict running minima -> smem records ----
        float runmin = INF;
        int mycnt = 0;
        for (int i0 = 0; i0 < cnt; i0 += 4) {
            int r = cnt - i0;
            int gg[4]; float4 bx[4], B[4], C[4];
            #pragma unroll
            for (int k = 0; k < 4; k++) {
                int idx = (k < r) ? (int)myidx[i0 + k] : 0;
                gg[k] = idx & (MAX_N - 1);
                bx[k] = __ldg(&g_prm[gg[k] * 4 + 0]);
                B[k]  = __ldg(&g_prm[gg[k] * 4 + 1]);
                C[k]  = __ldg(&g_prm[gg[k] * 4 + 2]);
            }
            #pragma unroll
            for (int k = 0; k < 4; k++) {
                float dx = px - B[k].x;
                float dy = py - B[k].y;
                float d2 = B[k].z * dx * dx + B[k].w * dx * dy + C[k].x * dy * dy;
                bool inb = (px >= bx[k].x) & (px <= bx[k].y) &
                           (py >= bx[k].z) & (py <= bx[k].w);
                bool acc = (k < r) & inb & (d2 < 9.0f) & (C[k].z < runmin);
                float a  = C[k].y * __expf(-0.5f * d2);  // speculative, MUFU
                if (acc) {
                    runmin = C[k].z;
                    if (mycnt < SLOTS) {
                        s_rec[entBase + mycnt * 32] = make_float2(C[k].z, a);
                        s_gid[entBase + mycnt * 32] = (unsigned short)gg[k];
                    }
                    mycnt++;
                }
            }
        }
        s_cnt[warp * 32 + lane] = min(mycnt, SLOTS);
        __syncthreads();

        // ---- phase B: ordered merge + branchless composite (warp 0) ----
        if (warp == 0) {
            float i0v = 0.0f, i1v = 0.0f, i2v = 0.0f;
            float ab = 0.0f;
            float d  = INF;
            #pragma unroll 1
            for (int s = 0; s < SEGS; s++) {
                int c = s_cnt[s * 32 + lane];
                int cmax = __reduce_max_sync(0xffffffffu, c);
                int base = s * SLOTS * 32 + lane;
                for (int j0 = 0; j0 < cmax; j0 += 4) {
                    float2 rec[4]; float4 col[4]; bool val[4];
                    #pragma unroll
                    for (int k = 0; k < 4; k++) {
                        int j = j0 + k;
                        int e = base + min(j, SLOTS - 1) * 32;
                        val[k] = (j < c);
                        rec[k] = s_rec[e];
                        int gid = (int)s_gid[e] & (MAX_N - 1);
                        col[k] = __ldg(&g_prm[gid * 4 + 3]);
                    }
                    #pragma unroll
                    for (int k = 0; k < 4; k++) {
                        bool t  = val[k] & (rec[k].x < d);
                        float na = t ? rec[k].y * (1.0f - ab) : 0.0f;
                        float om = 1.0f - na;
                        i0v = i0v * om + col[k].x * na;
                        i1v = i1v * om + col[k].y * na;
                        i2v = i2v * om + col[k].z * na;
                        ab += na;
                        d = t ? rec[k].x : d;
                    }
                }
            }
            int o = (py_i * IMG_W + px_i) * 3;
            out[o + 0] = i0v;
            out[o + 1] = i1v;
            out[o + 2] = i2v;
        }
        __syncthreads();   // protect s_tile / records before next iteration
    }
}

extern "C" void kernel_launch(void* const* d_in, const int* in_sizes, int n_in,
                              void* d_out, int out_size)
{
    const float* means  = (const float*)d_in[0];
    const float* scales = (const float*)d_in[1];
    const float* rots   = (const float*)d_in[2];
    const float* opac   = (const float*)d_in[3];
    const float* feats  = (const float*)d_in[4];
    const float* cam    = (const float*)d_in[5];
    const float* focal  = (const float*)d_in[6];
    const float* cx     = (const float*)d_in[7];
    const float* cy     = (const float*)d_in[8];
    float* out = (float*)d_out;

    int N = in_sizes[0] / 3;
    if (N > MAX_N) N = MAX_N;

    gs_precompute<<<(N + 255) / 256, 256>>>(means, scales, rots, opac, feats,
                                            cam, focal, cx, cy, N);

    int segLen = (N + SEGS - 1) / SEGS;
    size_t smem = (size_t)SEGS * SLOTS * 32 * sizeof(float2)          // 48 KB
                + (size_t)SEGS * 32 * sizeof(int)                     //  2 KB
                + (size_t)SEGS * SLOTS * 32 * sizeof(unsigned short)  // 12 KB
                + (size_t)SEGS * segLen * sizeof(unsigned short);     //  8 KB
    cudaFuncSetAttribute(gs_render, cudaFuncAttributeMaxDynamicSharedMemorySize,
                         72 * 1024);

    dim3 block(SEGS * 32, 1);
    gs_render<<<NPERS, block, smem>>>(out, N);
}

// round 9
// speedup vs baseline: 1.0416x; 1.0416x over previous
#include <cuda_runtime.h>
#include <math.h>

#define IMG_W 128
#define IMG_H 128
#define MAX_N 4096
#define TILE_W 8
#define TILE_H 4
#define SEGS   16
#define SLOTS  12
#define NTILES ((IMG_W / TILE_W) * (IMG_H / TILE_H))   // 512

// Packed hot params, 2 x float4 per gaussian:
//  [0] u, v, ia, ibc
//  [1] idd, op, z, bbox packed as uchar4 (minu, maxu, minv, maxv)
__device__ float4 g_pk[MAX_N * 2];
// Colors (phase B only).
__device__ float4 g_col[MAX_N];
// Tightened cull box (refbox ∩ 3-sigma ellipse extents) - cull only.
__device__ float4 g_cbox[MAX_N];

// Center-out orderings for tile coordinates (hot tiles in wave 1).
__constant__ int ord16[16] = {8,7,9,6,10,5,11,4,12,3,13,2,14,1,15,0};
__constant__ int ord32[32] = {16,15,17,14,18,13,19,12,20,11,21,10,22,9,23,8,
                              24,7,25,6,26,5,27,4,28,3,29,2,30,1,31,0};

__global__ void gs_precompute(const float* __restrict__ means,
                              const float* __restrict__ scales,
                              const float* __restrict__ rots,
                              const float* __restrict__ opac,
                              const float* __restrict__ feats,
                              const float* __restrict__ cam,
                              const float* __restrict__ focal_p,
                              const float* __restrict__ cx_p,
                              const float* __restrict__ cy_p,
                              int N)
{
    int g = blockIdx.x * blockDim.x + threadIdx.x;
    if (g >= N) return;

    const float f  = focal_p[0];
    const float cx = cx_p[0];
    const float cy = cy_p[0];

    float R[3][3], t[3];
    #pragma unroll
    for (int i = 0; i < 3; i++) {
        #pragma unroll
        for (int k = 0; k < 3; k++) R[i][k] = cam[i * 4 + k];
        t[i] = cam[i * 4 + 3];
    }

    float mean[3], sc[3];
    #pragma unroll
    for (int k = 0; k < 3; k++) {
        mean[k] = means[g * 3 + k];
        sc[k]   = expf(scales[g * 3 + k]);
    }

    float qw = rots[g * 4 + 0], qx = rots[g * 4 + 1];
    float qy = rots[g * 4 + 2], qz = rots[g * 4 + 3];
    float two_s = 2.0f / (qw * qw + qx * qx + qy * qy + qz * qz);
    float xx = qx * qx * two_s, xy = qx * qy * two_s, xz = qx * qz * two_s;
    float yw = qy * qw * two_s, yy = qy * qy * two_s, yz = qy * qz * two_s;
    float zw = qz * qw * two_s, zz = qz * qz * two_s, xw = qx * qw * two_s;
    float M[3][3];
    M[0][0] = 1.0f - (yy + zz); M[0][1] = xy - zw;          M[0][2] = xz + yw;
    M[1][0] = xy + zw;          M[1][1] = 1.0f - (xx + zz); M[1][2] = yz - xw;
    M[2][0] = xz - yw;          M[2][1] = yz + xw;          M[2][2] = 1.0f - (xx + yy);

    float mc[3];
    #pragma unroll
    for (int i = 0; i < 3; i++)
        mc[i] = R[i][0] * mean[0] + R[i][1] * mean[1] + R[i][2] * mean[2] + t[i];
    float z = mc[2];
    float u = mc[0] / z * f + cx;
    float v = mc[1] / z * f + cy;

    float J0[3], J1[3];
    #pragma unroll
    for (int k = 0; k < 3; k++) {
        J0[k] = f * R[0][k] - cx * R[2][k];
        J1[k] = f * R[1][k] - cy * R[2][k];
    }

    float V0[3], V1[3];
    #pragma unroll
    for (int k = 0; k < 3; k++) {
        V0[k] = (J0[0] * M[0][k] + J0[1] * M[1][k] + J0[2] * M[2][k]) * sc[k];
        V1[k] = (J1[0] * M[0][k] + J1[1] * M[1][k] + J1[2] * M[2][k]) * sc[k];
    }

    float inv_z2 = 1.0f / (z * z);
    float a = (V0[0] * V0[0] + V0[1] * V0[1] + V0[2] * V0[2]) * inv_z2;
    float b = (V0[0] * V1[0] + V0[1] * V1[1] + V0[2] * V1[2]) * inv_z2;
    float d = (V1[0] * V1[0] + V1[1] * V1[1] + V1[2] * V1[2]) * inv_z2;
    float det = a * d - b * b;
    float ia  = d / det;
    float ibc = -(b + b) / det;
    float idd = a / det;

    float op = 1.0f / (1.0f + expf(-opac[g]));
    float c0 = 1.0f / (1.0f + expf(-feats[g * 3 + 0]));
    float c1 = 1.0f / (1.0f + expf(-feats[g * 3 + 1]));
    float c2 = 1.0f / (1.0f + expf(-feats[g * 3 + 2]));

    float smax = fmaxf(sc[0], fmaxf(sc[1], sc[2]));
    float radius = smax * f / z * 3.0f;

    float minu = fmaxf(0.0f, truncf(u - radius));
    float maxu = truncf(u + radius);
    float minv = fmaxf(0.0f, truncf(v - radius));
    float maxv = truncf(v + radius);

    // pack bbox as bytes; clamps preserve exact comparisons for px,py in 0..127:
    //  - min* in [0,127] after cull for any surviving gaussian; clamping to 255
    //    makes never-overlapping gaussians always fail (they are culled anyway)
    //  - max* >= 0 after cull; values > 255 clamp to 255 (still > any px)
    unsigned pumin = (unsigned)fminf(minu, 255.0f);
    unsigned pumax = (unsigned)fminf(fmaxf(maxu, 0.0f), 255.0f);
    unsigned pvmin = (unsigned)fminf(minv, 255.0f);
    unsigned pvmax = (unsigned)fminf(fmaxf(maxv, 0.0f), 255.0f);
    unsigned pack = pumin | (pumax << 8) | (pvmin << 16) | (pvmax << 24);

    g_pk[g * 2 + 0] = make_float4(u, v, ia, ibc);
    g_pk[g * 2 + 1] = make_float4(idd, op, z, __uint_as_float(pack));
    g_col[g] = make_float4(c0, c1, c2, 0.0f);

    // tightened cull box: mask requires in_refbox AND d2<9;
    // d2<9 implies |dx| <= 3*sqrt(cov_xx), |dy| <= 3*sqrt(cov_yy)
    float ru = 3.0f * sqrtf(fmaxf(a, 0.0f));
    float rv = 3.0f * sqrtf(fmaxf(d, 0.0f));
    g_cbox[g] = make_float4(fmaxf(minu, u - ru), fminf(maxu, u + ru),
                            fmaxf(minv, v - rv), fminf(maxv, v + rv));
}

// One 8x4 tile per block (center-out bid->tile remap). 16 warps cull+scan
// 64-gaussian segments, record local strict-running-min candidates; warp 0
// merges segments in order (global running-min == reference depth_buf).
__global__ __launch_bounds__(SEGS * 32)
void gs_render(float* __restrict__ out, int N)
{
    extern __shared__ char smem_raw[];
    float2*         s_rec = (float2*)smem_raw;                  // 48 KB
    int*            s_cnt = (int*)(s_rec + SEGS * SLOTS * 32);  //  2 KB
    unsigned short* s_gid = (unsigned short*)(s_cnt + SEGS * 32); // 12 KB
    unsigned short* s_idx = s_gid + SEGS * SLOTS * 32;          //  2 KB

    const int warp = threadIdx.x >> 5;
    const int lane = threadIdx.x & 31;

    const int segLen = (N + SEGS - 1) / SEGS;
    const int segBeg = warp * segLen;
    const int segEnd = min(segBeg + segLen, N);
    const float INF = __int_as_float(0x7f800000);

    const int tile = blockIdx.x;
    const int tx0 = ord16[tile & 15] * TILE_W;
    const int ty0 = ord32[tile >> 4] * TILE_H;
    const int px_i = tx0 + (lane & (TILE_W - 1));
    const int py_i = ty0 + (lane >> 3);
    const float px = (float)px_i;
    const float py = (float)py_i;
    const float ftx0 = (float)tx0, ftx1 = (float)(tx0 + TILE_W - 1);
    const float fty0 = (float)ty0, fty1 = (float)(ty0 + TILE_H - 1);

    // ---- cull segment against tightened box (order-preserving) ----
    unsigned short* myidx = s_idx + warp * segLen;
    int cnt = 0;
    for (int j = segBeg; j < segEnd; j += 32) {
        int g = j + lane;
        bool ok = false;
        if (g < segEnd) {
            float4 cb = __ldg(&g_cbox[g]);
            ok = (cb.x <= ftx1) & (cb.y >= ftx0) &
                 (cb.z <= fty1) & (cb.w >= fty0);
        }
        unsigned m = __ballot_sync(0xffffffffu, ok);
        if (ok) myidx[cnt + __popc(m & ((1u << lane) - 1u))] = (unsigned short)g;
        cnt += __popc(m);
    }

    // ---- phase A: local strict running minima -> smem records ----
    const int entBase = warp * SLOTS * 32 + lane;
    float runmin = INF;
    int mycnt = 0;
    for (int i0 = 0; i0 < cnt; i0 += 4) {
        int r = cnt - i0;
        int gg[4]; float4 P1[4], P2[4];
        #pragma unroll
        for (int k = 0; k < 4; k++) {
            int idx = (k < r) ? (int)myidx[i0 + k] : 0;
            gg[k] = idx & (MAX_N - 1);
            P1[k] = __ldg(&g_pk[gg[k] * 2 + 0]);
            P2[k] = __ldg(&g_pk[gg[k] * 2 + 1]);
        }
        #pragma unroll
        for (int k = 0; k < 4; k++) {
            float dx = px - P1[k].x;
            float dy = py - P1[k].y;
            float d2 = P1[k].z * dx * dx + P1[k].w * dx * dy + P2[k].x * dy * dy;
            unsigned pk = __float_as_uint(P2[k].w);
            bool inb = (px_i >= (int)(pk & 0xFF)) &
                       (px_i <= (int)((pk >> 8) & 0xFF)) &
                       (py_i >= (int)((pk >> 16) & 0xFF)) &
                       (py_i <= (int)(pk >> 24));
            bool acc = (k < r) & inb & (d2 < 9.0f) & (P2[k].z < runmin);
            float a  = P2[k].y * __expf(-0.5f * d2);  // speculative, MUFU
            if (acc) {
                runmin = P2[k].z;
                if (mycnt < SLOTS) {
                    s_rec[entBase + mycnt * 32] = make_float2(P2[k].z, a);
                    s_gid[entBase + mycnt * 32] = (unsigned short)gg[k];
                }
                mycnt++;
            }
        }
    }
    s_cnt[warp * 32 + lane] = min(mycnt, SLOTS);
    __syncthreads();

    // ---- phase B: ordered merge + branchless composite (warp 0) ----
    if (warp == 0) {
        float i0v = 0.0f, i1v = 0.0f, i2v = 0.0f;
        float ab = 0.0f;
        float d  = INF;
        #pragma unroll 1
        for (int s = 0; s < SEGS; s++) {
            int c = s_cnt[s * 32 + lane];
            int cmax = __reduce_max_sync(0xffffffffu, c);
            int base = s * SLOTS * 32 + lane;
            for (int j0 = 0; j0 < cmax; j0 += 4) {
                float2 rec[4]; float4 col[4]; bool val[4];
                #pragma unroll
                for (int k = 0; k < 4; k++) {
                    int j = j0 + k;
                    int e = base + min(j, SLOTS - 1) * 32;
                    val[k] = (j < c);
                    rec[k] = s_rec[e];
                    int gid = (int)s_gid[e] & (MAX_N - 1);
                    col[k] = __ldg(&g_col[gid]);
                }
                #pragma unroll
                for (int k = 0; k < 4; k++) {
                    bool t  = val[k] & (rec[k].x < d);
                    float na = t ? rec[k].y * (1.0f - ab) : 0.0f;
                    float om = 1.0f - na;
                    i0v = i0v * om + col[k].x * na;
                    i1v = i1v * om + col[k].y * na;
                    i2v = i2v * om + col[k].z * na;
                    ab += na;
                    d = t ? rec[k].x : d;
                }
            }
        }
        int o = (py_i * IMG_W + px_i) * 3;
        out[o + 0] = i0v;
        out[o + 1] = i1v;
        out[o + 2] = i2v;
    }
}

extern "C" void kernel_launch(void* const* d_in, const int* in_sizes, int n_in,
                              void* d_out, int out_size)
{
    const float* means  = (const float*)d_in[0];
    const float* scales = (const float*)d_in[1];
    const float* rots   = (const float*)d_in[2];
    const float* opac   = (const float*)d_in[3];
    const float* feats  = (const float*)d_in[4];
    const float* cam    = (const float*)d_in[5];
    const float* focal  = (const float*)d_in[6];
    const float* cx     = (const float*)d_in[7];
    const float* cy     = (const float*)d_in[8];
    float* out = (float*)d_out;

    int N = in_sizes[0] / 3;
    if (N > MAX_N) N = MAX_N;

    gs_precompute<<<(N + 255) / 256, 256>>>(means, scales, rots, opac, feats,
                                            cam, focal, cx, cy, N);

    int segLen = (N + SEGS - 1) / SEGS;
    size_t smem = (size_t)SEGS * SLOTS * 32 * sizeof(float2)
                + (size_t)SEGS * 32 * sizeof(int)
                + (size_t)SEGS * SLOTS * 32 * sizeof(unsigned short)
                + (size_t)SEGS * segLen * sizeof(unsigned short);
    cudaFuncSetAttribute(gs_render, cudaFuncAttributeMaxDynamicSharedMemorySize,
                         72 * 1024);

    dim3 block(SEGS * 32, 1);
    gs_render<<<NTILES, block, smem>>>(out, N);
}

// round 10
// speedup vs baseline: 1.2679x; 1.2173x over previous
#include <cuda_runtime.h>
#include <math.h>

#define IMG_W 128
#define IMG_H 128
#define MAX_N 4096
#define TILE_W 8
#define TILE_H 4
#define SEGS   16
#define SLOTS  12
#define NTILES ((IMG_W / TILE_W) * (IMG_H / TILE_H))   // 512

// Per-gaussian params, 4 x float4:
//  [0] minu, maxu, minv, maxv    (reference box - used in pixel mask)
//  [1] u, v, ia, ibc
//  [2] idd, op, z, pad
//  [3] col0, col1, col2, pad
__device__ float4 g_prm[MAX_N * 4];
// Tightened cull box (refbox ∩ 3-sigma ellipse extents) - cull only.
__device__ float4 g_cbox[MAX_N];

__global__ void gs_precompute(const float* __restrict__ means,
                              const float* __restrict__ scales,
                              const float* __restrict__ rots,
                              const float* __restrict__ opac,
                              const float* __restrict__ feats,
                              const float* __restrict__ cam,
                              const float* __restrict__ focal_p,
                              const float* __restrict__ cx_p,
                              const float* __restrict__ cy_p,
                              int N)
{
    int g = blockIdx.x * blockDim.x + threadIdx.x;
    if (g >= N) return;

    const float f  = focal_p[0];
    const float cx = cx_p[0];
    const float cy = cy_p[0];

    float R[3][3], t[3];
    #pragma unroll
    for (int i = 0; i < 3; i++) {
        #pragma unroll
        for (int k = 0; k < 3; k++) R[i][k] = cam[i * 4 + k];
        t[i] = cam[i * 4 + 3];
    }

    float mean[3], sc[3];
    #pragma unroll
    for (int k = 0; k < 3; k++) {
        mean[k] = means[g * 3 + k];
        sc[k]   = expf(scales[g * 3 + k]);
    }

    float qw = rots[g * 4 + 0], qx = rots[g * 4 + 1];
    float qy = rots[g * 4 + 2], qz = rots[g * 4 + 3];
    float two_s = 2.0f / (qw * qw + qx * qx + qy * qy + qz * qz);
    float xx = qx * qx * two_s, xy = qx * qy * two_s, xz = qx * qz * two_s;
    float yw = qy * qw * two_s, yy = qy * qy * two_s, yz = qy * qz * two_s;
    float zw = qz * qw * two_s, zz = qz * qz * two_s, xw = qx * qw * two_s;
    float M[3][3];
    M[0][0] = 1.0f - (yy + zz); M[0][1] = xy - zw;          M[0][2] = xz + yw;
    M[1][0] = xy + zw;          M[1][1] = 1.0f - (xx + zz); M[1][2] = yz - xw;
    M[2][0] = xz - yw;          M[2][1] = yz + xw;          M[2][2] = 1.0f - (xx + yy);

    float mc[3];
    #pragma unroll
    for (int i = 0; i < 3; i++)
        mc[i] = R[i][0] * mean[0] + R[i][1] * mean[1] + R[i][2] * mean[2] + t[i];
    float z = mc[2];
    float u = mc[0] / z * f + cx;
    float v = mc[1] / z * f + cy;

    float J0[3], J1[3];
    #pragma unroll
    for (int k = 0; k < 3; k++) {
        J0[k] = f * R[0][k] - cx * R[2][k];
        J1[k] = f * R[1][k] - cy * R[2][k];
    }

    float V0[3], V1[3];
    #pragma unroll
    for (int k = 0; k < 3; k++) {
        V0[k] = (J0[0] * M[0][k] + J0[1] * M[1][k] + J0[2] * M[2][k]) * sc[k];
        V1[k] = (J1[0] * M[0][k] + J1[1] * M[1][k] + J1[2] * M[2][k]) * sc[k];
    }

    float inv_z2 = 1.0f / (z * z);
    float a = (V0[0] * V0[0] + V0[1] * V0[1] + V0[2] * V0[2]) * inv_z2;
    float b = (V0[0] * V1[0] + V0[1] * V1[1] + V0[2] * V1[2]) * inv_z2;
    float d = (V1[0] * V1[0] + V1[1] * V1[1] + V1[2] * V1[2]) * inv_z2;
    float det = a * d - b * b;
    float ia  = d / det;
    float ibc = -(b + b) / det;
    float idd = a / det;

    float op = 1.0f / (1.0f + expf(-opac[g]));
    float c0 = 1.0f / (1.0f + expf(-feats[g * 3 + 0]));
    float c1 = 1.0f / (1.0f + expf(-feats[g * 3 + 1]));
    float c2 = 1.0f / (1.0f + expf(-feats[g * 3 + 2]));

    float smax = fmaxf(sc[0], fmaxf(sc[1], sc[2]));
    float radius = smax * f / z * 3.0f;

    float minu = fmaxf(0.0f, truncf(u - radius));
    float maxu = truncf(u + radius);
    float minv = fmaxf(0.0f, truncf(v - radius));
    float maxv = truncf(v + radius);

    g_prm[g * 4 + 0] = make_float4(minu, maxu, minv, maxv);
    g_prm[g * 4 + 1] = make_float4(u, v, ia, ibc);
    g_prm[g * 4 + 2] = make_float4(idd, op, z, 0.0f);
    g_prm[g * 4 + 3] = make_float4(c0, c1, c2, 0.0f);

    // tightened cull box: mask requires in_refbox AND d2<9;
    // d2<9 implies |dx| <= 3*sqrt(cov_xx), |dy| <= 3*sqrt(cov_yy)
    float ru = 3.0f * sqrtf(fmaxf(a, 0.0f));
    float rv = 3.0f * sqrtf(fmaxf(d, 0.0f));
    g_cbox[g] = make_float4(fmaxf(minu, u - ru), fminf(maxu, u + ru),
                            fmaxf(minv, v - rv), fminf(maxv, v + rv));
}

// 16 warps / 8x4 tile. Phase A: per-warp segment cull + local strict-running-
// min records. Phase B (parallel): per-warp z-threshold from prefix of lastz,
// per-warp Tseg, prefix product -> T_in, per-warp affine fold (A, B); warp 0
// applies 16 affine maps in order. Exactly the reference recurrence
// (img' = img(1-na)+col*na, na = a*T, T' = T(1-a)) reassociated.
__global__ __launch_bounds__(SEGS * 32)
void gs_render(float* __restrict__ out, int N)
{
    extern __shared__ char smem_raw[];
    float2*         s_rec   = (float2*)smem_raw;                    // 48 KB
    float4*         s_AB    = (float4*)(s_rec + SEGS * SLOTS * 32); //  8 KB
    float*          s_lastz = (float*)(s_AB + SEGS * 32);           //  2 KB
    float*          s_Tseg  = s_lastz + SEGS * 32;                  //  2 KB
    int*            s_cnt   = (int*)(s_Tseg + SEGS * 32);           //  2 KB
    unsigned short* s_gid   = (unsigned short*)(s_cnt + SEGS * 32); // 12 KB
    unsigned short* s_idx   = s_gid + SEGS * SLOTS * 32;            //  2 KB

    const int warp = threadIdx.x >> 5;
    const int lane = threadIdx.x & 31;

    const int segLen = (N + SEGS - 1) / SEGS;
    const int segBeg = warp * segLen;
    const int segEnd = min(segBeg + segLen, N);
    const float INF = __int_as_float(0x7f800000);

    const int tile = blockIdx.x;
    const int tx0 = (tile & 15) * TILE_W;
    const int ty0 = (tile >> 4) * TILE_H;
    const int px_i = tx0 + (lane & (TILE_W - 1));
    const int py_i = ty0 + (lane >> 3);
    const float px = (float)px_i;
    const float py = (float)py_i;
    const float ftx0 = (float)tx0, ftx1 = (float)(tx0 + TILE_W - 1);
    const float fty0 = (float)ty0, fty1 = (float)(ty0 + TILE_H - 1);

    // ---- cull segment against tightened box (order-preserving) ----
    unsigned short* myidx = s_idx + warp * segLen;
    int cnt = 0;
    for (int j = segBeg; j < segEnd; j += 32) {
        int g = j + lane;
        bool ok = false;
        if (g < segEnd) {
            float4 cb = __ldg(&g_cbox[g]);
            ok = (cb.x <= ftx1) & (cb.y >= ftx0) &
                 (cb.z <= fty1) & (cb.w >= fty0);
        }
        unsigned m = __ballot_sync(0xffffffffu, ok);
        if (ok) myidx[cnt + __popc(m & ((1u << lane) - 1u))] = (unsigned short)g;
        cnt += __popc(m);
    }

    // ---- phase A: local strict running minima -> smem records ----
    const int entBase = warp * SLOTS * 32 + lane;
    float runmin = INF;
    float lastz  = INF;   // z of last STORED record
    int mycnt = 0;
    for (int i0 = 0; i0 < cnt; i0 += 4) {
        int r = cnt - i0;
        int gg[4]; float4 bx[4], B[4], C[4];
        #pragma unroll
        for (int k = 0; k < 4; k++) {
            int idx = (k < r) ? (int)myidx[i0 + k] : 0;
            gg[k] = idx & (MAX_N - 1);
            bx[k] = __ldg(&g_prm[gg[k] * 4 + 0]);
            B[k]  = __ldg(&g_prm[gg[k] * 4 + 1]);
            C[k]  = __ldg(&g_prm[gg[k] * 4 + 2]);
        }
        #pragma unroll
        for (int k = 0; k < 4; k++) {
            float dx = px - B[k].x;
            float dy = py - B[k].y;
            float d2 = B[k].z * dx * dx + B[k].w * dx * dy + C[k].x * dy * dy;
            bool inb = (px >= bx[k].x) & (px <= bx[k].y) &
                       (py >= bx[k].z) & (py <= bx[k].w);
            bool acc = (k < r) & inb & (d2 < 9.0f) & (C[k].z < runmin);
            float a  = C[k].y * __expf(-0.5f * d2);  // speculative, MUFU
            if (acc) {
                runmin = C[k].z;
                if (mycnt < SLOTS) {
                    s_rec[entBase + mycnt * 32] = make_float2(C[k].z, a);
                    s_gid[entBase + mycnt * 32] = (unsigned short)gg[k];
                    lastz = C[k].z;
                }
                mycnt++;
            }
        }
    }
    int c = min(mycnt, SLOTS);
    s_cnt[warp * 32 + lane]   = c;
    s_lastz[warp * 32 + lane] = lastz;
    __syncthreads();

    // ---- phase B1 (parallel): z-threshold + local transmittance Tseg ----
    float thr = INF;
    for (int s = 0; s < warp; s++)
        thr = fminf(thr, s_lastz[s * 32 + lane]);

    float T_run = thr;
    float Tseg = 1.0f;
    for (int j = 0; j < c; j++) {
        float2 rec = s_rec[entBase + j * 32];
        bool acc = rec.x < T_run;
        if (acc) { T_run = rec.x; Tseg *= (1.0f - rec.y); }
    }
    s_Tseg[warp * 32 + lane] = Tseg;
    __syncthreads();

    // ---- phase B2 (parallel): T_in prefix product + affine fold (A, B) ----
    float T_in = 1.0f;
    for (int s = 0; s < warp; s++)
        T_in *= s_Tseg[s * 32 + lane];

    float A = 1.0f, B0 = 0.0f, B1 = 0.0f, B2 = 0.0f;
    {
        float T = T_in;
        T_run = thr;
        for (int j0 = 0; j0 < c; j0 += 4) {
            float2 rec[4]; float4 col[4]; bool val[4];
            #pragma unroll
            for (int k = 0; k < 4; k++) {
                int j = j0 + k;
                int e = entBase + min(j, SLOTS - 1) * 32;
                val[k] = (j < c);
                rec[k] = s_rec[e];
                int gid = (int)s_gid[e] & (MAX_N - 1);
                col[k] = __ldg(&g_prm[gid * 4 + 3]);
            }
            #pragma unroll
            for (int k = 0; k < 4; k++) {
                bool acc = val[k] & (rec[k].x < T_run);
                float na = acc ? rec[k].y * T : 0.0f;
                float om = 1.0f - na;
                A  = A  * om;
                B0 = B0 * om + col[k].x * na;
                B1 = B1 * om + col[k].y * na;
                B2 = B2 * om + col[k].z * na;
                T  = T - na;                  // T' = T(1-a) = T - a*T
                T_run = acc ? rec[k].x : T_run;
            }
        }
    }
    s_AB[warp * 32 + lane] = make_float4(A, B0, B1, B2);
    // note: A stored for the combine; img' = A*img + (B0,B1,B2)
    __syncthreads();

    // ---- phase B3: apply 16 affine maps in order (warp 0) ----
    if (warp == 0) {
        float i0v = 0.0f, i1v = 0.0f, i2v = 0.0f;
        #pragma unroll
        for (int s = 0; s < SEGS; s++) {
            float4 ab = s_AB[s * 32 + lane];
            i0v = ab.x * i0v + ab.y;
            i1v = ab.x * i1v + ab.z;
            i2v = ab.x * i2v + ab.w;
        }
        int o = (py_i * IMG_W + px_i) * 3;
        out[o + 0] = i0v;
        out[o + 1] = i1v;
        out[o + 2] = i2v;
    }
}

extern "C" void kernel_launch(void* const* d_in, const int* in_sizes, int n_in,
                              void* d_out, int out_size)
{
    const float* means  = (const float*)d_in[0];
    const float* scales = (const float*)d_in[1];
    const float* rots   = (const float*)d_in[2];
    const float* opac   = (const float*)d_in[3];
    const float* feats  = (const float*)d_in[4];
    const float* cam    = (const float*)d_in[5];
    const float* focal  = (const float*)d_in[6];
    const float* cx     = (const float*)d_in[7];
    const float* cy     = (const float*)d_in[8];
    float* out = (float*)d_out;

    int N = in_sizes[0] / 3;
    if (N > MAX_N) N = MAX_N;

    gs_precompute<<<(N + 255) / 256, 256>>>(means, scales, rots, opac, feats,
                                            cam, focal, cx, cy, N);

    int segLen = (N + SEGS - 1) / SEGS;
    size_t smem = (size_t)SEGS * SLOTS * 32 * sizeof(float2)          // records
                + (size_t)SEGS * 32 * sizeof(float4)                  // A,B
                + (size_t)SEGS * 32 * sizeof(float) * 2               // lastz,Tseg
                + (size_t)SEGS * 32 * sizeof(int)                     // counts
                + (size_t)SEGS * SLOTS * 32 * sizeof(unsigned short)  // gids
                + (size_t)SEGS * segLen * sizeof(unsigned short);     // idx lists
    cudaFuncSetAttribute(gs_render, cudaFuncAttributeMaxDynamicSharedMemorySize,
                         96 * 1024);

    dim3 block(SEGS * 32, 1);
    gs_render<<<NTILES, block, smem>>>(out, N);
}